// round 14
// baseline (speedup 1.0000x reference)
#include <cuda_runtime.h>
#include <math.h>

typedef unsigned long long u64;
typedef unsigned int u32;

#define HH 128
#define WW 192
#define NA 9
#define NTOT (HH*WW*NA)      /* 221184 */
#define HW   (HH*WW)
#define PRE_K 6000
#define POST_K 300
#define NW 94                /* ceil(6000/64) */
#define NWP 96               /* padded row stride (u64 words) */
#define NBINS 65536
#define NB 128               /* blocks: <= SM count -> co-resident, gbar safe */
#define NT 256               /* threads per block */
#define NTHREADS (NB*NT)     /* 32768 */
#define NTILES 600           /* iou tiles: sum_{rg=0}^{11} (94-8rg) */

/* ---------------- scratch (no allocation allowed; BSS zero at load) ------ */
__device__ float4 g_boxes[NTOT];
__device__ __align__(16) u32 g_key[NTOT];
__device__ __align__(16) u32 g_hist[NBINS];
__device__ u32    g_binbase[NBINS];
__device__ u32    g_bincur[NBINS];
__device__ u32    g_blocksum[NB];
__device__ u32    g_boff[NB];
__device__ u32    g_threshbin;
__device__ u32    g_candcount;
__device__ u64    g_cand2[NTOT];
__device__ float4 g_nboxes[PRE_K];
__device__ u64    g_tvalid[NW];
__device__ u64    g_mask[(size_t)PRE_K * NWP];   /* 4.6 MB */
__device__ u32    g_barcnt[8];

__constant__ float c_anch[NA][4] = {
    {-84.f,  -40.f,  99.f,  55.f},
    {-176.f, -88.f,  191.f, 103.f},
    {-360.f, -184.f, 375.f, 199.f},
    {-56.f,  -56.f,  71.f,  71.f},
    {-120.f, -120.f, 135.f, 135.f},
    {-248.f, -248.f, 263.f, 263.f},
    {-36.f,  -80.f,  51.f,  95.f},
    {-80.f,  -168.f, 95.f,  183.f},
    {-168.f, -344.f, 183.f, 359.f}
};

/* iou tile row-group offsets: off[rg] = sum_{i<rg} (94-8i) */
__constant__ int c_toff[12] = {0,94,180,258,328,390,444,490,528,558,580,594};

/* ---------------- software global barrier (all NB blocks co-resident) ---- */
__device__ __forceinline__ void gbar(int ph) {
    __syncthreads();
    if (threadIdx.x == 0) {
        __threadfence();
        atomicAdd(&g_barcnt[ph], 1u);
        volatile u32* p = &g_barcnt[ph];
        while (*p < (u32)NB) __nanosleep(64);
        __threadfence();
    }
    __syncthreads();
}

__global__ void __launch_bounds__(NT)
mega_kernel(const float* __restrict__ scores,
            const float* __restrict__ deltas,
            const float* __restrict__ iminfo,
            float* __restrict__ out) {
    __shared__ u32 ss[NT];
    __shared__ float4 sb[64];
    __shared__ float  sa[64];
    __shared__ u64 s_keep[NW];
    __shared__ u32 s_pref[NW];

    const int t = threadIdx.x;
    const int blk = blockIdx.x;
    const int gtid = blk * NT + t;

    /* ============ A: zero hist + tvalid ============ */
    if (gtid < NBINS / 4) ((uint4*)g_hist)[gtid] = make_uint4(0u, 0u, 0u, 0u);
    else if (gtid - NBINS / 4 < NW) g_tvalid[gtid - NBINS / 4] = 0ull;
    gbar(0);

    /* ============ B: decode + histogram ============ */
    for (int i = gtid; i < NTOT; i += NTHREADS) {
        int a  = i / HW;
        int sp = i - a * HW;
        int y  = sp / WW;
        int x  = sp - y * WW;

        float sx = 16.f * (float)x;
        float sy = 16.f * (float)y;
        float ax1 = c_anch[a][0] + sx;
        float ay1 = c_anch[a][1] + sy;
        float aw  = (c_anch[a][2] - c_anch[a][0]) + 1.f;
        float ah  = (c_anch[a][3] - c_anch[a][1]) + 1.f;
        float cx  = __fadd_rn(ax1, 0.5f * aw);
        float cy  = __fadd_rn(ay1, 0.5f * ah);

        float dx = deltas[(4*a+0)*HW + sp];
        float dy = deltas[(4*a+1)*HW + sp];
        float dw = fminf(fmaxf(deltas[(4*a+2)*HW + sp], -10.f), 10.f);
        float dh = fminf(fmaxf(deltas[(4*a+3)*HW + sp], -10.f), 10.f);

        float pcx = __fadd_rn(__fmul_rn(dx, aw), cx);
        float pcy = __fadd_rn(__fmul_rn(dy, ah), cy);
        float pw  = __fmul_rn(expf(dw), aw);
        float ph  = __fmul_rn(expf(dh), ah);
        float hx  = __fmul_rn(0.5f, pw);
        float hy  = __fmul_rn(0.5f, ph);
        float x1 = __fsub_rn(pcx, hx), x2 = __fadd_rn(pcx, hx);
        float y1 = __fsub_rn(pcy, hy), y2 = __fadd_rn(pcy, hy);

        float xmax = __fsub_rn(iminfo[1], 1.f);
        float ymax = __fsub_rn(iminfo[0], 1.f);
        x1 = fminf(fmaxf(x1, 0.f), xmax);
        x2 = fminf(fmaxf(x2, 0.f), xmax);
        y1 = fminf(fmaxf(y1, 0.f), ymax);
        y2 = fminf(fmaxf(y2, 0.f), ymax);

        float minsz = __fmul_rn(16.f, iminfo[2]);
        bool valid = (__fadd_rn(__fsub_rn(x2, x1), 1.f) >= minsz) &&
                     (__fadd_rn(__fsub_rn(y2, y1), 1.f) >= minsz);

        float sc = scores[(NA + a)*HW + sp];
        u32 u = valid ? __float_as_uint(sc) : 0xFF800000u;
        u32 m = (u & 0x80000000u) ? ~u : (u | 0x80000000u);
        u32 key = ~m;                              /* big score -> small key */

        g_boxes[i] = make_float4(x1, y1, x2, y2);
        g_key[i]   = key;
        atomicAdd(&g_hist[key >> 16], 1u);
    }
    gbar(1);

    /* ============ C1: per-block bin sums (512 bins/block, 2/thread) ====== */
    int b0 = blk * 512 + 2 * t;
    u32 c0 = __ldcg(&g_hist[b0]);
    u32 c1 = __ldcg(&g_hist[b0 + 1]);
    u32 part = c0 + c1;
    ss[t] = part;
    __syncthreads();
    for (int off = 128; off > 0; off >>= 1) {
        if (t < off) ss[t] += ss[t + off];
        __syncthreads();
    }
    if (t == 0) g_blocksum[blk] = ss[0];
    gbar(2);

    /* ============ C2: block 0 scans 128 block sums ============ */
    if (blk == 0 && t == 0) {
        u32 run = 0;
        for (int b = 0; b < NB; b++) {
            u32 s = __ldcg(&g_blocksum[b]);
            g_boff[b] = run;
            run += s;
        }
    }
    gbar(3);

    /* ============ C3: per-bin exclusive prefix + threshbin ============ */
    ss[t] = part;
    __syncthreads();
    for (int off = 1; off < NT; off <<= 1) {
        u32 x = (t >= off) ? ss[t - off] : 0u;
        __syncthreads();
        ss[t] += x;
        __syncthreads();
    }
    {
        u32 excl = ss[t] - part + __ldcg(&g_boff[blk]);
        g_binbase[b0]     = excl;      g_bincur[b0]     = excl;
        g_binbase[b0 + 1] = excl + c0; g_bincur[b0 + 1] = excl + c0;
        if (c0 && excl < PRE_K && excl + c0 >= PRE_K) {
            g_threshbin = (u32)b0; g_candcount = excl + c0;
        }
        u32 e1 = excl + c0;
        if (c1 && e1 < PRE_K && e1 + c1 >= PRE_K) {
            g_threshbin = (u32)(b0 + 1); g_candcount = e1 + c1;
        }
    }
    gbar(4);

    /* ============ D: compact into bin-grouped slots ============ */
    {
        u32 tb = __ldcg(&g_threshbin);
        for (int q = gtid; q < NTOT / 4; q += NTHREADS) {
            uint4 k4 = ((const uint4*)g_key)[q];
            u32 ks[4] = {k4.x, k4.y, k4.z, k4.w};
            int i0 = q * 4;
            int a = i0 / HW, spb = i0 - a * HW;   /* quad never crosses a-plane */
            #pragma unroll
            for (int e = 0; e < 4; e++) {
                u32 bin = ks[e] >> 16;
                if (bin <= tb) {
                    u32 pos = atomicAdd(&g_bincur[bin], 1u);
                    u32 orig = (u32)((spb + e) * NA + a);
                    g_cand2[pos] = ((u64)ks[e] << 32) | orig;
                }
            }
        }
    }
    gbar(5);

    /* ============ E: exact rank within coarse bin + gather ============ */
    {
        u32 cnt = __ldcg(&g_candcount);
        if ((gtid & 3) == 0) {
            for (u32 s = (u32)(gtid >> 2); s < cnt; s += NTHREADS / 4) {
                u64 mine = __ldcg((const unsigned long long*)&g_cand2[s]);
                u32 key = (u32)(mine >> 32);
                u32 bin = key >> 16;
                u32 lo = __ldcg(&g_binbase[bin]);
                u32 hi = __ldcg(&g_bincur[bin]);
                u32 r = 0;
                for (u32 j = lo; j < hi; j++)
                    r += (__ldcg((const unsigned long long*)&g_cand2[j]) < mine) ? 1u : 0u;
                u32 grank = lo + r;
                if (grank < PRE_K) {
                    u32 orig = (u32)mine;
                    int aa = orig % NA;
                    int sp = orig / NA;
                    g_nboxes[grank] = g_boxes[aa * HW + sp];
                    if (key < 0xFF800000u)
                        atomicOr(&g_tvalid[grank >> 6], 1ull << (grank & 63));
                }
            }
        }
    }
    gbar(6);

    /* ============ F: IoU tiles (64 cols x 512 rows, 2 rows/thread) ======= */
    for (int tile = blk; tile < NTILES; tile += NB) {
        int rg = 11;
        while (c_toff[rg] > tile) rg--;
        int cb = 8 * rg + (tile - c_toff[rg]);

        if (t < 64) {
            int j = cb * 64 + t;
            float4 bj = (j < PRE_K) ? g_nboxes[j] : make_float4(0.f, 0.f, 0.f, 0.f);
            sb[t] = bj;
            sa[t] = __fmul_rn(__fsub_rn(bj.z, bj.x), __fsub_rn(bj.w, bj.y));
        }
        __syncthreads();

        int i0 = rg * 512 + t;
        int i1 = i0 + 256;
        float4 v0 = (i0 < PRE_K) ? g_nboxes[i0] : make_float4(0.f, 0.f, 0.f, 0.f);
        float4 v1 = (i1 < PRE_K) ? g_nboxes[i1] : make_float4(0.f, 0.f, 0.f, 0.f);
        float a0 = __fmul_rn(__fsub_rn(v0.z, v0.x), __fsub_rn(v0.w, v0.y));
        float a1 = __fmul_rn(__fsub_rn(v1.z, v1.x), __fsub_rn(v1.w, v1.y));

        u64 bits0 = 0ull, bits1 = 0ull;
        int cmax = PRE_K - cb * 64; if (cmax > 64) cmax = 64;
        for (int c = 0; c < cmax; ++c) {
            float4 bc = sb[c];
            float ac = sa[c];
            {
                float lx = fmaxf(v0.x, bc.x), ly = fmaxf(v0.y, bc.y);
                float rx = fminf(v0.z, bc.z), ry = fminf(v0.w, bc.w);
                float w = fmaxf(__fsub_rn(rx, lx), 0.f);
                float h = fmaxf(__fsub_rn(ry, ly), 0.f);
                float inter = __fmul_rn(w, h);
                float denom = __fsub_rn(__fadd_rn(a0, ac), inter);
                float d = __fmaf_rn(-0.7f, denom, inter);
                bool dec = d > 0.f;
                if (fabsf(d) < 1e-6f * denom) dec = (inter / denom) > 0.7f;
                if (dec) bits0 |= (1ull << c);
            }
            {
                float lx = fmaxf(v1.x, bc.x), ly = fmaxf(v1.y, bc.y);
                float rx = fminf(v1.z, bc.z), ry = fminf(v1.w, bc.w);
                float w = fmaxf(__fsub_rn(rx, lx), 0.f);
                float h = fmaxf(__fsub_rn(ry, ly), 0.f);
                float inter = __fmul_rn(w, h);
                float denom = __fsub_rn(__fadd_rn(a1, ac), inter);
                float d = __fmaf_rn(-0.7f, denom, inter);
                bool dec = d > 0.f;
                if (fabsf(d) < 1e-6f * denom) dec = (inter / denom) > 0.7f;
                if (dec) bits1 |= (1ull << c);
            }
        }
        if (i0 < PRE_K) g_mask[(size_t)i0 * NWP + cb] = bits0;
        if (i1 < PRE_K) g_mask[(size_t)i1 * NWP + cb] = bits1;
        __syncthreads();
    }
    gbar(7);

    /* ============ G: single-warp greedy NMS + output (block 0) =========== */
    if (blk != 0) return;
    if (t >= 32) return;
    {
        const unsigned FULL = 0xffffffffu;
        int lane = t;

        float4* o4 = (float4*)out;
        for (int i = lane; i < (POST_K * 5) / 4; i += 32)
            o4[i] = make_float4(0.f, 0.f, 0.f, 0.f);
        __syncwarp();

        int w0 = 3 * lane;
        bool h1 = (w0 + 1) < NW, h2 = (w0 + 2) < NW;
        u64 rm0 = 0, rm1 = 0, rm2 = 0;
        u64 km0 = 0, km1 = 0, km2 = 0;
        u64 tv0 = __ldcg((const unsigned long long*)&g_tvalid[w0]);
        u64 tv1 = h1 ? __ldcg((const unsigned long long*)&g_tvalid[w0 + 1]) : 0ull;
        u64 tv2 = h2 ? __ldcg((const unsigned long long*)&g_tvalid[w0 + 2]) : 0ull;
        int kept_total = 0;

        int pr = 2 * lane;
        u64 m0 = __ldcg((const unsigned long long*)&g_mask[(size_t)pr * NWP + 0]);
        u64 m1 = __ldcg((const unsigned long long*)&g_mask[(size_t)(pr + 1) * NWP + 0]);

        for (int c = 0; c < NW; ++c) {
            u64 n0 = 0ull, n1 = 0ull;
            if (c + 1 < NW) {
                int rr = (c + 1) * 64 + 2 * lane;
                if (rr     < PRE_K) n0 = __ldcg((const unsigned long long*)&g_mask[(size_t)rr       * NWP + (c + 1)]);
                if (rr + 1 < PRE_K) n1 = __ldcg((const unsigned long long*)&g_mask[(size_t)(rr + 1) * NWP + (c + 1)]);
            }

            int owner = c / 3;
            int slot  = c - 3 * owner;
            u64 myrem = (slot == 0) ? rm0 : ((slot == 1) ? rm1 : rm2);
            u64 mytv  = (slot == 0) ? tv0 : ((slot == 1) ? tv1 : tv2);
            u64 rem_c = __shfl_sync(FULL, myrem, owner);
            u64 tv_c  = __shfl_sync(FULL, mytv,  owner);

            u64 local = rem_c, keptmask = 0ull;
            u64 mb = tv_c & ~local;
            while (mb) {
                int k = __ffsll((long long)mb) - 1;
                u64 v = __shfl_sync(FULL, (k & 1) ? m1 : m0, k >> 1);
                keptmask |= (1ull << k);
                local |= v;
                mb = tv_c & ~local & ~((2ull << k) - 1ull);
            }

            if (lane == owner) {
                if (slot == 0) km0 = keptmask;
                else if (slot == 1) km1 = keptmask;
                else km2 = keptmask;
            }
            kept_total += __popcll(keptmask);
            if (kept_total >= POST_K) break;

            if (w0 + 2 > c) {
                u64 mbf = keptmask;
                while (mbf) {
                    int rk[8];
                    #pragma unroll
                    for (int q = 0; q < 8; q++) {
                        if (mbf) { rk[q] = __ffsll((long long)mbf) - 1; mbf &= mbf - 1; }
                        else rk[q] = -1;
                    }
                    u64 o0 = 0ull, o1 = 0ull, o2 = 0ull;
                    #pragma unroll
                    for (int q = 0; q < 8; q++) {
                        if (rk[q] >= 0) {
                            const u64* p = &g_mask[(size_t)(c * 64 + rk[q]) * NWP + w0];
                            o0 |= __ldcg((const unsigned long long*)&p[0]);
                            if (h1) o1 |= __ldcg((const unsigned long long*)&p[1]);
                            if (h2) o2 |= __ldcg((const unsigned long long*)&p[2]);
                        }
                    }
                    rm0 |= o0; rm1 |= o1; rm2 |= o2;
                }
            }
            m0 = n0; m1 = n1;
        }

        s_keep[w0] = km0;
        if (h1) s_keep[w0 + 1] = km1;
        if (h2) s_keep[w0 + 2] = km2;
        __syncwarp();
        if (lane == 0) {
            u32 run = 0;
            for (int w = 0; w < NW; ++w) { s_pref[w] = run; run += (u32)__popcll(s_keep[w]); }
        }
        __syncwarp();
        for (int i = lane; i < PRE_K; i += 32) {
            int w = i >> 6, b = i & 63;
            if (s_pref[w] >= POST_K) break;
            u64 kw = s_keep[w];
            if ((kw >> b) & 1ull) {
                u64 lowmask = (b == 0) ? 0ull : ((~0ull) >> (64 - b));
                u32 rank = s_pref[w] + (u32)__popcll(kw & lowmask);
                if (rank < POST_K) {
                    float4 bx = g_nboxes[i];
                    out[rank * 5 + 1] = bx.x;
                    out[rank * 5 + 2] = bx.y;
                    out[rank * 5 + 3] = bx.z;
                    out[rank * 5 + 4] = bx.w;
                }
            }
        }

        /* reset barrier counters for the next (deterministic) replay */
        if (lane == 0) {
            #pragma unroll
            for (int i = 0; i < 8; i++) g_barcnt[i] = 0u;
        }
    }
}

/* ---------------- launch (ONE kernel) ---------------- */
extern "C" void kernel_launch(void* const* d_in, const int* in_sizes, int n_in,
                              void* d_out, int out_size) {
    const float* scores = (const float*)d_in[0];
    const float* deltas = (const float*)d_in[1];
    const float* iminfo = (const float*)d_in[2];
    float* out = (float*)d_out;

    mega_kernel<<<NB, NT>>>(scores, deltas, iminfo, out);
}

// round 15
// speedup vs baseline: 1.6330x; 1.6330x over previous
#include <cuda_runtime.h>
#include <math.h>

typedef unsigned long long u64;
typedef unsigned int u32;

#define HH 128
#define WW 192
#define NA 9
#define NTOT (HH*WW*NA)      /* 221184 */
#define HW   (HH*WW)
#define PRE_K 6000
#define POST_K 300
#define NW 94                /* ceil(6000/64) */
#define NWP 96               /* padded row stride (u64 words) */
#define NBINS 65536
#define SORT_CAP 8192
#define NTRI 2256            /* upper-tri iou blocks: sum_{r=0}^{46}(94-2r) */

/* ---------------- scratch (no allocation allowed) ---------------- */
__device__ float4 g_boxes[NTOT];       /* (a, sp) layout */
__device__ __align__(16) u32 g_key[NTOT];
__device__ __align__(16) u32 g_hist[NBINS];
__device__ __align__(16) u32 g_fhist[NBINS];
__device__ __align__(16) u32 g_fstart[NBINS];
__device__ __align__(16) u32 g_fcur[NBINS];
__device__ u32    g_threshbin;
__device__ u32    g_binlo;
__device__ u32    g_candcount;
__device__ u64    g_cand[SORT_CAP];
__device__ u64    g_cand2[SORT_CAP];
__device__ float4 g_nboxes[PRE_K];
__device__ u64    g_tvalid[NW];
__device__ u64    g_mask[(size_t)PRE_K * NWP];   /* 4.6 MB */

/* fine bin: 26 high key bits, relative to first active coarse bin, clamped.
   Monotone non-decreasing in key -> exact ranks for ANY distribution.      */
__device__ __forceinline__ u32 fine_of(u32 key, u32 lo) {
    u32 f = (key >> 6) - (lo << 10);
    return (f > 65535u) ? 65535u : f;
}

/* anchors from _generate_anchors(16,(.5,1,2),(8,16,32)) */
__constant__ float c_anch[NA][4] = {
    {-84.f,  -40.f,  99.f,  55.f},
    {-176.f, -88.f,  191.f, 103.f},
    {-360.f, -184.f, 375.f, 199.f},
    {-56.f,  -56.f,  71.f,  71.f},
    {-120.f, -120.f, 135.f, 135.f},
    {-248.f, -248.f, 263.f, 263.f},
    {-36.f,  -80.f,  51.f,  95.f},
    {-80.f,  -168.f, 95.f,  183.f},
    {-168.f, -344.f, 183.f, 359.f}
};

/* ---------------- K0: init scratch ---------------- */
__global__ void init_kernel() {
    int i = blockIdx.x * 256 + threadIdx.x;
    if (i < NBINS / 4) { ((uint4*)g_hist)[i] = make_uint4(0u, 0u, 0u, 0u); return; }
    int j = i - NBINS / 4;
    if (j < NBINS / 4) { ((uint4*)g_fhist)[j] = make_uint4(0u, 0u, 0u, 0u); return; }
    j -= NBINS / 4;
    if (j < NW) { g_tvalid[j] = 0ull; return; }
    j -= NW;
    if (j == 0) g_candcount = 0u;
    else if (j == 1) g_binlo = 0xFFFFFFFFu;
}
#define INIT_ITEMS (NBINS/4 + NBINS/4 + NW + 2)

/* ---------------- K1: decode + score key + histogram (coalesced) --------- */
__global__ void decode_kernel(const float* __restrict__ scores,
                              const float* __restrict__ deltas,
                              const float* __restrict__ iminfo) {
    int tid = blockIdx.x * 256 + threadIdx.x;     /* grid covers NTOT exactly */
    int a  = tid / HW;
    int sp = tid - a * HW;
    int y  = sp / WW;
    int x  = sp - y * WW;

    float sx = 16.f * (float)x;
    float sy = 16.f * (float)y;
    float ax1 = c_anch[a][0] + sx;
    float ay1 = c_anch[a][1] + sy;
    float aw  = (c_anch[a][2] - c_anch[a][0]) + 1.f;
    float ah  = (c_anch[a][3] - c_anch[a][1]) + 1.f;
    float cx  = __fadd_rn(ax1, 0.5f * aw);
    float cy  = __fadd_rn(ay1, 0.5f * ah);

    float dx = deltas[(4*a+0)*HW + sp];
    float dy = deltas[(4*a+1)*HW + sp];
    float dw = fminf(fmaxf(deltas[(4*a+2)*HW + sp], -10.f), 10.f);
    float dh = fminf(fmaxf(deltas[(4*a+3)*HW + sp], -10.f), 10.f);

    float pcx = __fadd_rn(__fmul_rn(dx, aw), cx);
    float pcy = __fadd_rn(__fmul_rn(dy, ah), cy);
    float pw  = __fmul_rn(expf(dw), aw);
    float ph  = __fmul_rn(expf(dh), ah);
    float hx  = __fmul_rn(0.5f, pw);
    float hy  = __fmul_rn(0.5f, ph);
    float x1 = __fsub_rn(pcx, hx), x2 = __fadd_rn(pcx, hx);
    float y1 = __fsub_rn(pcy, hy), y2 = __fadd_rn(pcy, hy);

    float xmax = __fsub_rn(iminfo[1], 1.f);
    float ymax = __fsub_rn(iminfo[0], 1.f);
    x1 = fminf(fmaxf(x1, 0.f), xmax);
    x2 = fminf(fmaxf(x2, 0.f), xmax);
    y1 = fminf(fmaxf(y1, 0.f), ymax);
    y2 = fminf(fmaxf(y2, 0.f), ymax);

    float minsz = __fmul_rn(16.f, iminfo[2]);
    bool valid = (__fadd_rn(__fsub_rn(x2, x1), 1.f) >= minsz) &&
                 (__fadd_rn(__fsub_rn(y2, y1), 1.f) >= minsz);

    float sc = scores[(NA + a)*HW + sp];
    u32 u = valid ? __float_as_uint(sc) : 0xFF800000u;
    u32 m = (u & 0x80000000u) ? ~u : (u | 0x80000000u);
    u32 key = ~m;                                  /* big score -> small key */

    g_boxes[tid] = make_float4(x1, y1, x2, y2);
    g_key[tid]   = key;
    atomicAdd(&g_hist[key >> 16], 1u);
}

/* ---------------- K2: threshold bin + first active bin ---------------- */
__global__ void __launch_bounds__(1024) scan_kernel() {
    __shared__ u32 ss[1024];
    int t = threadIdx.x;
    int base = t * 64;
    u32 v = 0;
    const uint4* h4 = (const uint4*)&g_hist[base];
    #pragma unroll 16
    for (int b = 0; b < 16; b++) {
        uint4 q = h4[b];
        v += q.x + q.y + q.z + q.w;
    }
    ss[t] = v;
    __syncthreads();
    for (int off = 1; off < 1024; off <<= 1) {
        u32 x = (t >= off) ? ss[t - off] : 0u;
        __syncthreads();
        ss[t] += x;
        __syncthreads();
    }
    u32 incl = ss[t], excl = incl - v;
    if (excl < PRE_K && incl >= PRE_K) {
        u32 cum = excl;
        for (int b = 0; b < 64; b++) {
            cum += g_hist[base + b];
            if (cum >= PRE_K) { g_threshbin = (u32)(base + b); break; }
        }
    }
    /* first nonzero bin overall -> g_binlo */
    if (v) {
        for (int b = 0; b < 64; b++) {
            if (g_hist[base + b]) { atomicMin(&g_binlo, (u32)(base + b)); break; }
        }
    }
}

/* ---------------- K3: compact (uint4 keys, block atomic) + fine hist ----- */
__global__ void compact_kernel() {
    __shared__ u32 sbase;
    __shared__ u32 scnt;
    int tid = blockIdx.x * 256 + threadIdx.x;      /* covers NTOT/4 exactly */
    if (threadIdx.x == 0) scnt = 0u;
    __syncthreads();
    uint4 k4 = ((const uint4*)g_key)[tid];
    u32 tb = g_threshbin;
    u32 lo = g_binlo;
    u32 ks0 = k4.x, ks1 = k4.y, ks2 = k4.z, ks3 = k4.w;
    int n = ((ks0 >> 16) <= tb) + ((ks1 >> 16) <= tb) +
            ((ks2 >> 16) <= tb) + ((ks3 >> 16) <= tb);
    u32 pos = 0;
    if (n) pos = atomicAdd(&scnt, (u32)n);
    __syncthreads();
    if (threadIdx.x == 0) sbase = atomicAdd(&g_candcount, scnt);
    __syncthreads();
    if (n) {
        int i0 = tid * 4;
        int a = i0 / HW, spb = i0 - a * HW;        /* uint4 never crosses a-plane */
        u32 base = sbase + pos;
        u32 ks[4] = {ks0, ks1, ks2, ks3};
        #pragma unroll
        for (int e = 0; e < 4; e++) {
            if ((ks[e] >> 16) <= tb) {
                u32 orig = (u32)((spb + e) * NA + a);
                if (base < SORT_CAP) g_cand[base] = ((u64)ks[e] << 32) | orig;
                base++;
                atomicAdd(&g_fhist[fine_of(ks[e], lo)], 1u);
            }
        }
    }
}

/* ---------------- K4: fine prefix + scatter + rank + gather (1 block) ---- */
__global__ void __launch_bounds__(1024) finesort_kernel() {
    __shared__ u32 ss[1024];
    int t = threadIdx.x;
    int base = t * 64;
    const uint4* h4 = (const uint4*)&g_fhist[base];

    /* pass 1: sum this thread's 64 bin counts (rolling register quad) */
    u32 v = 0;
    #pragma unroll 16
    for (int b = 0; b < 16; b++) {
        uint4 q = h4[b];
        v += q.x + q.y + q.z + q.w;
    }

    ss[t] = v;
    __syncthreads();
    for (int off = 1; off < 1024; off <<= 1) {
        u32 x = (t >= off) ? ss[t - off] : 0u;
        __syncthreads();
        ss[t] += x;
        __syncthreads();
    }
    u32 run = ss[t] - v;                 /* exclusive prefix for this thread */

    /* pass 2: reload counts (L2-hot), write fstart/fcur vectorized */
    uint4* fs4 = (uint4*)&g_fstart[base];
    uint4* fc4 = (uint4*)&g_fcur[base];
    #pragma unroll 16
    for (int b = 0; b < 16; b++) {
        uint4 q = h4[b];
        uint4 s;
        s.x = run;
        s.y = s.x + q.x;
        s.z = s.y + q.y;
        s.w = s.z + q.z;
        run = s.w + q.w;
        fs4[b] = s;
        fc4[b] = s;
    }
    __syncthreads();

    /* scatter candidates into fine-bin-grouped order */
    u32 cnt = g_candcount; if (cnt > SORT_CAP) cnt = SORT_CAP;
    u32 lo = g_binlo;
    for (u32 i = t; i < cnt; i += 1024) {
        u64 v64 = g_cand[i];
        u32 fine = fine_of((u32)(v64 >> 32), lo);
        u32 pos = atomicAdd(&g_fcur[fine], 1u);
        g_cand2[pos] = v64;
    }
    __syncthreads();

    /* exact rank within tiny fine bin + direct gather/scatter */
    for (u32 i = t; i < cnt; i += 1024) {
        u64 mine = g_cand2[i];
        u32 key = (u32)(mine >> 32);
        u32 fine = fine_of(key, lo);
        u32 start = g_fstart[fine];
        u32 end   = g_fcur[fine];                  /* = start + bin count */
        u32 r = 0;
        for (u32 j = start; j < end; j++) r += (g_cand2[j] < mine) ? 1u : 0u;
        u32 grank = start + r;
        if (grank < PRE_K) {
            u32 orig = (u32)mine;
            int aa = orig % NA;
            int sp = orig / NA;
            g_nboxes[grank] = g_boxes[aa * HW + sp];
            if (key < 0xFF800000u)
                atomicOr(&g_tvalid[grank >> 6], 1ull << (grank & 63));
        }
    }
}

/* ---------------- K5: IoU bitmask, exact triangular grid ----------------- */
__global__ void iou_kernel() {
    __shared__ float4 sb[64];
    __shared__ float  sa[64];
    int bid = blockIdx.x, t = threadIdx.x;        /* 64 threads */
    /* invert bid -> (rb, cb): offset(r) = 95r - r^2 (validated in R7) */
    int rb = (int)((95.0 - sqrt(9025.0 - 4.0 * (double)bid)) * 0.5);
    while (95 * (rb + 1) - (rb + 1) * (rb + 1) <= bid) rb++;
    while (95 * rb - rb * rb > bid) rb--;
    int cb = 2 * rb + (bid - (95 * rb - rb * rb));

    int j = cb * 64 + t;
    float4 bj = (j < PRE_K) ? g_nboxes[j] : make_float4(0.f, 0.f, 0.f, 0.f);
    sb[t] = bj;
    sa[t] = __fmul_rn(__fsub_rn(bj.z, bj.x), __fsub_rn(bj.w, bj.y));
    __syncthreads();

    int i0 = rb * 128 + t;
    int i1 = i0 + 64;
    bool do1 = (cb >= 2 * rb + 1);
    float4 b0 = (i0 < PRE_K) ? g_nboxes[i0] : make_float4(0.f, 0.f, 0.f, 0.f);
    float4 b1 = (do1 && i1 < PRE_K) ? g_nboxes[i1] : make_float4(0.f, 0.f, 0.f, 0.f);
    float a0 = __fmul_rn(__fsub_rn(b0.z, b0.x), __fsub_rn(b0.w, b0.y));
    float a1 = __fmul_rn(__fsub_rn(b1.z, b1.x), __fsub_rn(b1.w, b1.y));

    u64 bits0 = 0ull, bits1 = 0ull;
    int cmax = PRE_K - cb * 64; if (cmax > 64) cmax = 64;
    for (int c = 0; c < cmax; ++c) {
        float4 bc = sb[c];
        float ac = sa[c];
        {
            float lx = fmaxf(b0.x, bc.x), ly = fmaxf(b0.y, bc.y);
            float rx = fminf(b0.z, bc.z), ry = fminf(b0.w, bc.w);
            float w = fmaxf(__fsub_rn(rx, lx), 0.f);
            float h = fmaxf(__fsub_rn(ry, ly), 0.f);
            float inter = __fmul_rn(w, h);
            float denom = __fsub_rn(__fadd_rn(a0, ac), inter);
            /* decision-exact: |d| >= 1e-6*denom decides sign of (iou-0.7) */
            float d = __fmaf_rn(-0.7f, denom, inter);
            bool dec = d > 0.f;
            if (fabsf(d) < 1e-6f * denom) dec = (inter / denom) > 0.7f;
            if (dec) bits0 |= (1ull << c);
        }
        {
            float lx = fmaxf(b1.x, bc.x), ly = fmaxf(b1.y, bc.y);
            float rx = fminf(b1.z, bc.z), ry = fminf(b1.w, bc.w);
            float w = fmaxf(__fsub_rn(rx, lx), 0.f);
            float h = fmaxf(__fsub_rn(ry, ly), 0.f);
            float inter = __fmul_rn(w, h);
            float denom = __fsub_rn(__fadd_rn(a1, ac), inter);
            float d = __fmaf_rn(-0.7f, denom, inter);
            bool dec = d > 0.f;
            if (fabsf(d) < 1e-6f * denom) dec = (inter / denom) > 0.7f;
            if (dec) bits1 |= (1ull << c);
        }
    }
    if (i0 < PRE_K) g_mask[(size_t)i0 * NWP + cb] = bits0;
    if (do1 && i1 < PRE_K) g_mask[(size_t)i1 * NWP + cb] = bits1;
}

/* ---------------- K6: single-warp greedy NMS scan + output (fused) ------- */
__global__ void nms_out_kernel(float* __restrict__ out) {
    const unsigned FULL = 0xffffffffu;
    __shared__ u64 s_keep[NW];
    __shared__ u32 s_pref[NW];
    int lane = threadIdx.x;

    /* zero output (1500 floats = 375 float4) */
    float4* o4 = (float4*)out;
    for (int i = lane; i < (POST_K * 5) / 4; i += 32) o4[i] = make_float4(0.f, 0.f, 0.f, 0.f);
    __syncwarp();

    int w0 = 3 * lane;
    bool h1 = (w0 + 1) < NW, h2 = (w0 + 2) < NW;
    u64 rm0 = 0, rm1 = 0, rm2 = 0;
    u64 km0 = 0, km1 = 0, km2 = 0;
    u64 tv0 = g_tvalid[w0];
    u64 tv1 = h1 ? g_tvalid[w0 + 1] : 0ull;
    u64 tv2 = h2 ? g_tvalid[w0 + 2] : 0ull;
    int kept_total = 0;

    int pr = 2 * lane;
    u64 m0 = g_mask[(size_t)pr * NWP + 0];
    u64 m1 = g_mask[(size_t)(pr + 1) * NWP + 0];

    for (int c = 0; c < NW; ++c) {
        u64 n0 = 0ull, n1 = 0ull;
        if (c + 1 < NW) {
            int rr = (c + 1) * 64 + 2 * lane;
            if (rr     < PRE_K) n0 = g_mask[(size_t)rr       * NWP + (c + 1)];
            if (rr + 1 < PRE_K) n1 = g_mask[(size_t)(rr + 1) * NWP + (c + 1)];
        }

        int owner = c / 3;
        int slot  = c - 3 * owner;
        u64 myrem = (slot == 0) ? rm0 : ((slot == 1) ? rm1 : rm2);
        u64 mytv  = (slot == 0) ? tv0 : ((slot == 1) ? tv1 : tv2);
        u64 rem_c = __shfl_sync(FULL, myrem, owner);
        u64 tv_c  = __shfl_sync(FULL, mytv,  owner);

        u64 local = rem_c, keptmask = 0ull;
        u64 mb = tv_c & ~local;
        while (mb) {
            int k = __ffsll((long long)mb) - 1;
            u64 v = __shfl_sync(FULL, (k & 1) ? m1 : m0, k >> 1);
            keptmask |= (1ull << k);
            local |= v;
            mb = tv_c & ~local & ~((2ull << k) - 1ull);
        }

        if (lane == owner) {
            if (slot == 0) km0 = keptmask;
            else if (slot == 1) km1 = keptmask;
            else km2 = keptmask;
        }
        kept_total += __popcll(keptmask);
        if (kept_total >= POST_K) break;

        if (w0 + 2 > c) {
            u64 mbf = keptmask;
            while (mbf) {
                int rk[8];
                #pragma unroll
                for (int q = 0; q < 8; q++) {
                    if (mbf) { rk[q] = __ffsll((long long)mbf) - 1; mbf &= mbf - 1; }
                    else rk[q] = -1;
                }
                u64 o0 = 0ull, o1 = 0ull, o2 = 0ull;
                #pragma unroll
                for (int q = 0; q < 8; q++) {
                    if (rk[q] >= 0) {
                        const u64* p = &g_mask[(size_t)(c * 64 + rk[q]) * NWP + w0];
                        o0 |= p[0];
                        if (h1) o1 |= p[1];
                        if (h2) o2 |= p[2];
                    }
                }
                rm0 |= o0; rm1 |= o1; rm2 |= o2;
            }
        }
        m0 = n0; m1 = n1;
    }

    /* publish keep masks + prefix, then emit first 300 kept boxes */
    s_keep[w0] = km0;
    if (h1) s_keep[w0 + 1] = km1;
    if (h2) s_keep[w0 + 2] = km2;
    __syncwarp();
    if (lane == 0) {
        u32 run = 0;
        for (int w = 0; w < NW; ++w) { s_pref[w] = run; run += (u32)__popcll(s_keep[w]); }
    }
    __syncwarp();
    for (int i = lane; i < PRE_K; i += 32) {
        int w = i >> 6, b = i & 63;
        if (s_pref[w] >= POST_K) break;
        u64 kw = s_keep[w];
        if ((kw >> b) & 1ull) {
            u64 lowmask = (b == 0) ? 0ull : ((~0ull) >> (64 - b));
            u32 rank = s_pref[w] + (u32)__popcll(kw & lowmask);
            if (rank < POST_K) {
                float4 bx = g_nboxes[i];
                out[rank * 5 + 1] = bx.x;
                out[rank * 5 + 2] = bx.y;
                out[rank * 5 + 3] = bx.z;
                out[rank * 5 + 4] = bx.w;
            }
        }
    }
}

/* ---------------- launch (7 kernels) ---------------- */
extern "C" void kernel_launch(void* const* d_in, const int* in_sizes, int n_in,
                              void* d_out, int out_size) {
    const float* scores = (const float*)d_in[0];
    const float* deltas = (const float*)d_in[1];
    const float* iminfo = (const float*)d_in[2];
    float* out = (float*)d_out;

    init_kernel<<<(INIT_ITEMS + 255) / 256, 256>>>();
    decode_kernel<<<NTOT / 256, 256>>>(scores, deltas, iminfo);
    scan_kernel<<<1, 1024>>>();
    compact_kernel<<<(NTOT / 4) / 256, 256>>>();
    finesort_kernel<<<1, 1024>>>();
    iou_kernel<<<NTRI, 64>>>();
    nms_out_kernel<<<1, 32>>>(out);
}

// round 16
// speedup vs baseline: 1.8597x; 1.1388x over previous
#include <cuda_runtime.h>
#include <math.h>

typedef unsigned long long u64;
typedef unsigned int u32;

#define HH 128
#define WW 192
#define NA 9
#define NTOT (HH*WW*NA)      /* 221184 */
#define HW   (HH*WW)
#define PRE_K 6000
#define POST_K 300
#define NW 94                /* ceil(6000/64) */
#define NWP 96               /* padded row stride (u64 words) */
#define NBINS 65536
#define NFBINS 16384
#define SORT_CAP 8192
#define NTRI 2256            /* upper-tri iou blocks: sum_{r=0}^{46}(94-2r) */
#define NCHUNK 64            /* scan: 64 blocks x 1024 bins */

/* ---------------- scratch (no allocation allowed) ---------------- */
__device__ float4 g_boxes[NTOT];       /* (a, sp) layout */
__device__ __align__(16) u32 g_key[NTOT];
__device__ __align__(16) u32 g_hist[NBINS];
__device__ __align__(16) u32 g_fhist[NFBINS];
__device__ __align__(16) u32 g_fstart[NFBINS];
__device__ __align__(16) u32 g_fcur[NFBINS];
__device__ u32    g_chunksum[NCHUNK];
__device__ u32    g_scandone;
__device__ u32    g_threshbin;
__device__ u32    g_binlo;
__device__ u32    g_candcount;
__device__ u64    g_cand[SORT_CAP];
__device__ u64    g_cand2[SORT_CAP];
__device__ float4 g_nboxes[PRE_K];
__device__ u64    g_tvalid[NW];
__device__ u64    g_mask[(size_t)PRE_K * NWP];   /* 4.6 MB */

/* fine bin: 26 high key bits relative to first active coarse bin, clamped.
   Monotone non-decreasing in key -> exact ranks for ANY distribution
   (clamped tail bin is ranked by within-bin brute force).                 */
__device__ __forceinline__ u32 fine_of(u32 key, u32 lo) {
    u32 f = (key >> 6) - (lo << 10);
    return (f > (u32)(NFBINS - 1)) ? (u32)(NFBINS - 1) : f;
}

/* anchors from _generate_anchors(16,(.5,1,2),(8,16,32)) */
__constant__ float c_anch[NA][4] = {
    {-84.f,  -40.f,  99.f,  55.f},
    {-176.f, -88.f,  191.f, 103.f},
    {-360.f, -184.f, 375.f, 199.f},
    {-56.f,  -56.f,  71.f,  71.f},
    {-120.f, -120.f, 135.f, 135.f},
    {-248.f, -248.f, 263.f, 263.f},
    {-36.f,  -80.f,  51.f,  95.f},
    {-80.f,  -168.f, 95.f,  183.f},
    {-168.f, -344.f, 183.f, 359.f}
};

/* ---------------- K0: init scratch ---------------- */
__global__ void init_kernel() {
    int i = blockIdx.x * 256 + threadIdx.x;
    if (i < NBINS / 4) { ((uint4*)g_hist)[i] = make_uint4(0u, 0u, 0u, 0u); return; }
    int j = i - NBINS / 4;
    if (j < NFBINS / 4) { ((uint4*)g_fhist)[j] = make_uint4(0u, 0u, 0u, 0u); return; }
    j -= NFBINS / 4;
    if (j < NW) { g_tvalid[j] = 0ull; return; }
    j -= NW;
    if (j == 0) g_candcount = 0u;
    else if (j == 1) g_binlo = 0xFFFFFFFFu;
    else if (j == 2) g_scandone = 0u;
}
#define INIT_ITEMS (NBINS/4 + NFBINS/4 + NW + 3)

/* ---------------- K1: decode + score key + histogram (coalesced) --------- */
__global__ void decode_kernel(const float* __restrict__ scores,
                              const float* __restrict__ deltas,
                              const float* __restrict__ iminfo) {
    int tid = blockIdx.x * 256 + threadIdx.x;     /* grid covers NTOT exactly */
    int a  = tid / HW;
    int sp = tid - a * HW;
    int y  = sp / WW;
    int x  = sp - y * WW;

    float sx = 16.f * (float)x;
    float sy = 16.f * (float)y;
    float ax1 = c_anch[a][0] + sx;
    float ay1 = c_anch[a][1] + sy;
    float aw  = (c_anch[a][2] - c_anch[a][0]) + 1.f;
    float ah  = (c_anch[a][3] - c_anch[a][1]) + 1.f;
    float cx  = __fadd_rn(ax1, 0.5f * aw);
    float cy  = __fadd_rn(ay1, 0.5f * ah);

    float dx = deltas[(4*a+0)*HW + sp];
    float dy = deltas[(4*a+1)*HW + sp];
    float dw = fminf(fmaxf(deltas[(4*a+2)*HW + sp], -10.f), 10.f);
    float dh = fminf(fmaxf(deltas[(4*a+3)*HW + sp], -10.f), 10.f);

    float pcx = __fadd_rn(__fmul_rn(dx, aw), cx);
    float pcy = __fadd_rn(__fmul_rn(dy, ah), cy);
    float pw  = __fmul_rn(expf(dw), aw);
    float ph  = __fmul_rn(expf(dh), ah);
    float hx  = __fmul_rn(0.5f, pw);
    float hy  = __fmul_rn(0.5f, ph);
    float x1 = __fsub_rn(pcx, hx), x2 = __fadd_rn(pcx, hx);
    float y1 = __fsub_rn(pcy, hy), y2 = __fadd_rn(pcy, hy);

    float xmax = __fsub_rn(iminfo[1], 1.f);
    float ymax = __fsub_rn(iminfo[0], 1.f);
    x1 = fminf(fmaxf(x1, 0.f), xmax);
    x2 = fminf(fmaxf(x2, 0.f), xmax);
    y1 = fminf(fmaxf(y1, 0.f), ymax);
    y2 = fminf(fmaxf(y2, 0.f), ymax);

    float minsz = __fmul_rn(16.f, iminfo[2]);
    bool valid = (__fadd_rn(__fsub_rn(x2, x1), 1.f) >= minsz) &&
                 (__fadd_rn(__fsub_rn(y2, y1), 1.f) >= minsz);

    float sc = scores[(NA + a)*HW + sp];
    u32 u = valid ? __float_as_uint(sc) : 0xFF800000u;
    u32 m = (u & 0x80000000u) ? ~u : (u | 0x80000000u);
    u32 key = ~m;                                  /* big score -> small key */

    g_boxes[tid] = make_float4(x1, y1, x2, y2);
    g_key[tid]   = key;
    atomicAdd(&g_hist[key >> 16], 1u);
}

/* ---------------- K2: parallel threshold scan (64 blocks) ---------------- */
/* Each block sums its 1024-bin chunk + finds its first nonzero bin; the
   last-finished block locates the rank-PRE_K crossing chunk, then block-
   scans that chunk's 1024 bins for the exact threshold bin.               */
__global__ void __launch_bounds__(256) scan_kernel() {
    __shared__ u32 ssum[256];
    __shared__ u32 smin[256];
    __shared__ bool s_last;
    __shared__ u32 s_excl;
    __shared__ int s_chunk;
    int t = threadIdx.x;
    int chunk = blockIdx.x;
    int base = chunk * 1024 + t * 4;

    uint4 q = *(const uint4*)&g_hist[base];
    u32 v = q.x + q.y + q.z + q.w;
    u32 mb = 0xFFFFFFFFu;
    if      (q.x) mb = (u32)base;
    else if (q.y) mb = (u32)base + 1;
    else if (q.z) mb = (u32)base + 2;
    else if (q.w) mb = (u32)base + 3;

    ssum[t] = v; smin[t] = mb;
    __syncthreads();
    for (int off = 128; off > 0; off >>= 1) {
        if (t < off) {
            ssum[t] += ssum[t + off];
            smin[t] = min(smin[t], smin[t + off]);
        }
        __syncthreads();
    }
    if (t == 0) {
        g_chunksum[chunk] = ssum[0];
        if (smin[0] != 0xFFFFFFFFu) atomicMin(&g_binlo, smin[0]);
        __threadfence();
        s_last = (atomicAdd(&g_scandone, 1u) == NCHUNK - 1);
    }
    __syncthreads();
    if (!s_last) return;
    __threadfence();

    if (t == 0) {
        u32 run = 0;
        for (int c = 0; c < NCHUNK; c++) {
            u32 s = __ldcg(&g_chunksum[c]);
            if (run < PRE_K && run + s >= PRE_K) { s_chunk = c; s_excl = run; break; }
            run += s;
        }
    }
    __syncthreads();

    /* exact bin inside crossing chunk */
    int cbase = s_chunk * 1024 + t * 4;
    uint4 qc = *(const uint4*)&g_hist[cbase];
    u32 vc = qc.x + qc.y + qc.z + qc.w;
    ssum[t] = vc;
    __syncthreads();
    for (int off = 1; off < 256; off <<= 1) {
        u32 x = (t >= off) ? ssum[t - off] : 0u;
        __syncthreads();
        ssum[t] += x;
        __syncthreads();
    }
    u32 cum = s_excl + (ssum[t] - vc);
    u32 cs[4] = {qc.x, qc.y, qc.z, qc.w};
    #pragma unroll
    for (int e = 0; e < 4; e++) {
        if (cum < PRE_K && cum + cs[e] >= PRE_K) g_threshbin = (u32)(cbase + e);
        cum += cs[e];
    }
}

/* ---------------- K3: compact (uint4 keys, block atomic) + fine hist ----- */
__global__ void compact_kernel() {
    __shared__ u32 sbase;
    __shared__ u32 scnt;
    int tid = blockIdx.x * 256 + threadIdx.x;      /* covers NTOT/4 exactly */
    if (threadIdx.x == 0) scnt = 0u;
    __syncthreads();
    uint4 k4 = ((const uint4*)g_key)[tid];
    u32 tb = g_threshbin;
    u32 lo = g_binlo;
    u32 ks0 = k4.x, ks1 = k4.y, ks2 = k4.z, ks3 = k4.w;
    int n = ((ks0 >> 16) <= tb) + ((ks1 >> 16) <= tb) +
            ((ks2 >> 16) <= tb) + ((ks3 >> 16) <= tb);
    u32 pos = 0;
    if (n) pos = atomicAdd(&scnt, (u32)n);
    __syncthreads();
    if (threadIdx.x == 0) sbase = atomicAdd(&g_candcount, scnt);
    __syncthreads();
    if (n) {
        int i0 = tid * 4;
        int a = i0 / HW, spb = i0 - a * HW;        /* uint4 never crosses a-plane */
        u32 base = sbase + pos;
        u32 ks[4] = {ks0, ks1, ks2, ks3};
        #pragma unroll
        for (int e = 0; e < 4; e++) {
            if ((ks[e] >> 16) <= tb) {
                u32 orig = (u32)((spb + e) * NA + a);
                if (base < SORT_CAP) g_cand[base] = ((u64)ks[e] << 32) | orig;
                base++;
                atomicAdd(&g_fhist[fine_of(ks[e], lo)], 1u);
            }
        }
    }
}

/* ---------------- K4: fine prefix + scatter + rank + gather (1 block) ---- */
/* 16384 bins / 1024 threads = 16 bins (4 uint4) per thread.                */
__global__ void __launch_bounds__(1024) finesort_kernel() {
    __shared__ u32 ss[1024];
    int t = threadIdx.x;
    int base = t * 16;
    const uint4* h4 = (const uint4*)&g_fhist[base];

    /* pass 1: sum this thread's 16 bin counts */
    u32 v = 0;
    #pragma unroll 4
    for (int b = 0; b < 4; b++) {
        uint4 q = h4[b];
        v += q.x + q.y + q.z + q.w;
    }

    ss[t] = v;
    __syncthreads();
    for (int off = 1; off < 1024; off <<= 1) {
        u32 x = (t >= off) ? ss[t - off] : 0u;
        __syncthreads();
        ss[t] += x;
        __syncthreads();
    }
    u32 run = ss[t] - v;                 /* exclusive prefix for this thread */

    /* pass 2: reload counts (L1/L2-hot), write fstart/fcur vectorized */
    uint4* fs4 = (uint4*)&g_fstart[base];
    uint4* fc4 = (uint4*)&g_fcur[base];
    #pragma unroll 4
    for (int b = 0; b < 4; b++) {
        uint4 q = h4[b];
        uint4 s;
        s.x = run;
        s.y = s.x + q.x;
        s.z = s.y + q.y;
        s.w = s.z + q.z;
        run = s.w + q.w;
        fs4[b] = s;
        fc4[b] = s;
    }
    __syncthreads();

    /* scatter candidates into fine-bin-grouped order */
    u32 cnt = g_candcount; if (cnt > SORT_CAP) cnt = SORT_CAP;
    u32 lo = g_binlo;
    for (u32 i = t; i < cnt; i += 1024) {
        u64 v64 = g_cand[i];
        u32 fine = fine_of((u32)(v64 >> 32), lo);
        u32 pos = atomicAdd(&g_fcur[fine], 1u);
        g_cand2[pos] = v64;
    }
    __syncthreads();

    /* exact rank within tiny fine bin + direct gather/scatter */
    for (u32 i = t; i < cnt; i += 1024) {
        u64 mine = g_cand2[i];
        u32 key = (u32)(mine >> 32);
        u32 fine = fine_of(key, lo);
        u32 start = g_fstart[fine];
        u32 end   = g_fcur[fine];                  /* = start + bin count */
        u32 r = 0;
        for (u32 j = start; j < end; j++) r += (g_cand2[j] < mine) ? 1u : 0u;
        u32 grank = start + r;
        if (grank < PRE_K) {
            u32 orig = (u32)mine;
            int aa = orig % NA;
            int sp = orig / NA;
            g_nboxes[grank] = g_boxes[aa * HW + sp];
            if (key < 0xFF800000u)
                atomicOr(&g_tvalid[grank >> 6], 1ull << (grank & 63));
        }
    }
}

/* ---------------- K5: IoU bitmask, exact triangular grid ----------------- */
__global__ void iou_kernel() {
    __shared__ float4 sb[64];
    __shared__ float  sa[64];
    int bid = blockIdx.x, t = threadIdx.x;        /* 64 threads */
    /* invert bid -> (rb, cb): offset(r) = 95r - r^2 (validated in R7) */
    int rb = (int)((95.0 - sqrt(9025.0 - 4.0 * (double)bid)) * 0.5);
    while (95 * (rb + 1) - (rb + 1) * (rb + 1) <= bid) rb++;
    while (95 * rb - rb * rb > bid) rb--;
    int cb = 2 * rb + (bid - (95 * rb - rb * rb));

    int j = cb * 64 + t;
    float4 bj = (j < PRE_K) ? g_nboxes[j] : make_float4(0.f, 0.f, 0.f, 0.f);
    sb[t] = bj;
    sa[t] = __fmul_rn(__fsub_rn(bj.z, bj.x), __fsub_rn(bj.w, bj.y));
    __syncthreads();

    int i0 = rb * 128 + t;
    int i1 = i0 + 64;
    bool do1 = (cb >= 2 * rb + 1);
    float4 b0 = (i0 < PRE_K) ? g_nboxes[i0] : make_float4(0.f, 0.f, 0.f, 0.f);
    float4 b1 = (do1 && i1 < PRE_K) ? g_nboxes[i1] : make_float4(0.f, 0.f, 0.f, 0.f);
    float a0 = __fmul_rn(__fsub_rn(b0.z, b0.x), __fsub_rn(b0.w, b0.y));
    float a1 = __fmul_rn(__fsub_rn(b1.z, b1.x), __fsub_rn(b1.w, b1.y));

    u64 bits0 = 0ull, bits1 = 0ull;
    int cmax = PRE_K - cb * 64; if (cmax > 64) cmax = 64;
    for (int c = 0; c < cmax; ++c) {
        float4 bc = sb[c];
        float ac = sa[c];
        {
            float lx = fmaxf(b0.x, bc.x), ly = fmaxf(b0.y, bc.y);
            float rx = fminf(b0.z, bc.z), ry = fminf(b0.w, bc.w);
            float w = fmaxf(__fsub_rn(rx, lx), 0.f);
            float h = fmaxf(__fsub_rn(ry, ly), 0.f);
            float inter = __fmul_rn(w, h);
            float denom = __fsub_rn(__fadd_rn(a0, ac), inter);
            /* decision-exact: |d| >= 1e-6*denom decides sign of (iou-0.7) */
            float d = __fmaf_rn(-0.7f, denom, inter);
            bool dec = d > 0.f;
            if (fabsf(d) < 1e-6f * denom) dec = (inter / denom) > 0.7f;
            if (dec) bits0 |= (1ull << c);
        }
        {
            float lx = fmaxf(b1.x, bc.x), ly = fmaxf(b1.y, bc.y);
            float rx = fminf(b1.z, bc.z), ry = fminf(b1.w, bc.w);
            float w = fmaxf(__fsub_rn(rx, lx), 0.f);
            float h = fmaxf(__fsub_rn(ry, ly), 0.f);
            float inter = __fmul_rn(w, h);
            float denom = __fsub_rn(__fadd_rn(a1, ac), inter);
            float d = __fmaf_rn(-0.7f, denom, inter);
            bool dec = d > 0.f;
            if (fabsf(d) < 1e-6f * denom) dec = (inter / denom) > 0.7f;
            if (dec) bits1 |= (1ull << c);
        }
    }
    if (i0 < PRE_K) g_mask[(size_t)i0 * NWP + cb] = bits0;
    if (do1 && i1 < PRE_K) g_mask[(size_t)i1 * NWP + cb] = bits1;
}

/* ---------------- K6: single-warp greedy NMS scan + output (fused) ------- */
__global__ void nms_out_kernel(float* __restrict__ out) {
    const unsigned FULL = 0xffffffffu;
    __shared__ u64 s_keep[NW];
    __shared__ u32 s_pref[NW];
    int lane = threadIdx.x;

    /* zero output (1500 floats = 375 float4) */
    float4* o4 = (float4*)out;
    for (int i = lane; i < (POST_K * 5) / 4; i += 32) o4[i] = make_float4(0.f, 0.f, 0.f, 0.f);
    __syncwarp();

    int w0 = 3 * lane;
    bool h1 = (w0 + 1) < NW, h2 = (w0 + 2) < NW;
    u64 rm0 = 0, rm1 = 0, rm2 = 0;
    u64 km0 = 0, km1 = 0, km2 = 0;
    u64 tv0 = g_tvalid[w0];
    u64 tv1 = h1 ? g_tvalid[w0 + 1] : 0ull;
    u64 tv2 = h2 ? g_tvalid[w0 + 2] : 0ull;
    int kept_total = 0;

    int pr = 2 * lane;
    u64 m0 = g_mask[(size_t)pr * NWP + 0];
    u64 m1 = g_mask[(size_t)(pr + 1) * NWP + 0];

    for (int c = 0; c < NW; ++c) {
        u64 n0 = 0ull, n1 = 0ull;
        if (c + 1 < NW) {
            int rr = (c + 1) * 64 + 2 * lane;
            if (rr     < PRE_K) n0 = g_mask[(size_t)rr       * NWP + (c + 1)];
            if (rr + 1 < PRE_K) n1 = g_mask[(size_t)(rr + 1) * NWP + (c + 1)];
        }

        int owner = c / 3;
        int slot  = c - 3 * owner;
        u64 myrem = (slot == 0) ? rm0 : ((slot == 1) ? rm1 : rm2);
        u64 mytv  = (slot == 0) ? tv0 : ((slot == 1) ? tv1 : tv2);
        u64 rem_c = __shfl_sync(FULL, myrem, owner);
        u64 tv_c  = __shfl_sync(FULL, mytv,  owner);

        u64 local = rem_c, keptmask = 0ull;
        u64 mb = tv_c & ~local;
        while (mb) {
            int k = __ffsll((long long)mb) - 1;
            u64 v = __shfl_sync(FULL, (k & 1) ? m1 : m0, k >> 1);
            keptmask |= (1ull << k);
            local |= v;
            mb = tv_c & ~local & ~((2ull << k) - 1ull);
        }

        if (lane == owner) {
            if (slot == 0) km0 = keptmask;
            else if (slot == 1) km1 = keptmask;
            else km2 = keptmask;
        }
        kept_total += __popcll(keptmask);
        if (kept_total >= POST_K) break;

        if (w0 + 2 > c) {
            u64 mbf = keptmask;
            while (mbf) {
                int rk[8];
                #pragma unroll
                for (int q = 0; q < 8; q++) {
                    if (mbf) { rk[q] = __ffsll((long long)mbf) - 1; mbf &= mbf - 1; }
                    else rk[q] = -1;
                }
                u64 o0 = 0ull, o1 = 0ull, o2 = 0ull;
                #pragma unroll
                for (int q = 0; q < 8; q++) {
                    if (rk[q] >= 0) {
                        const u64* p = &g_mask[(size_t)(c * 64 + rk[q]) * NWP + w0];
                        o0 |= p[0];
                        if (h1) o1 |= p[1];
                        if (h2) o2 |= p[2];
                    }
                }
                rm0 |= o0; rm1 |= o1; rm2 |= o2;
            }
        }
        m0 = n0; m1 = n1;
    }

    /* publish keep masks + prefix, then emit first 300 kept boxes */
    s_keep[w0] = km0;
    if (h1) s_keep[w0 + 1] = km1;
    if (h2) s_keep[w0 + 2] = km2;
    __syncwarp();
    if (lane == 0) {
        u32 run = 0;
        for (int w = 0; w < NW; ++w) { s_pref[w] = run; run += (u32)__popcll(s_keep[w]); }
    }
    __syncwarp();
    for (int i = lane; i < PRE_K; i += 32) {
        int w = i >> 6, b = i & 63;
        if (s_pref[w] >= POST_K) break;
        u64 kw = s_keep[w];
        if ((kw >> b) & 1ull) {
            u64 lowmask = (b == 0) ? 0ull : ((~0ull) >> (64 - b));
            u32 rank = s_pref[w] + (u32)__popcll(kw & lowmask);
            if (rank < POST_K) {
                float4 bx = g_nboxes[i];
                out[rank * 5 + 1] = bx.x;
                out[rank * 5 + 2] = bx.y;
                out[rank * 5 + 3] = bx.z;
                out[rank * 5 + 4] = bx.w;
            }
        }
    }
}

/* ---------------- launch (7 kernels) ---------------- */
extern "C" void kernel_launch(void* const* d_in, const int* in_sizes, int n_in,
                              void* d_out, int out_size) {
    const float* scores = (const float*)d_in[0];
    const float* deltas = (const float*)d_in[1];
    const float* iminfo = (const float*)d_in[2];
    float* out = (float*)d_out;

    init_kernel<<<(INIT_ITEMS + 255) / 256, 256>>>();
    decode_kernel<<<NTOT / 256, 256>>>(scores, deltas, iminfo);
    scan_kernel<<<NCHUNK, 256>>>();
    compact_kernel<<<(NTOT / 4) / 256, 256>>>();
    finesort_kernel<<<1, 1024>>>();
    iou_kernel<<<NTRI, 64>>>();
    nms_out_kernel<<<1, 32>>>(out);
}